// round 1
// baseline (speedup 1.0000x reference)
#include <cuda_runtime.h>
#include <cuda_bf16.h>

// FlashAttention varlen prefill, GQA 16/4, D=128, sliding window 1024, softcap 30.
// Round 1: fp32 SIMT flash kernel with online softmax. BQ=64 x BK=64 tiles,
// 256 threads, register-blocked 2x8 QK micro-tile + 2x16 PV micro-tile.

#define NH      16
#define NKV     4
#define HD      128
#define BQ      64
#define BK      64
#define DPAD    132   // K/V/Q smem row stride (floats) -- conflict-free LDS.128
#define PPAD    68    // P smem row stride
#define NTH     256
#define WINDOW  1024
#define SOFTCAPV 30.0f
#define NEGV    (-1e30f)
#define QK_SCALE 0.08838834764831845f   // 1/sqrt(128)

#define SMEM_BYTES ((BQ*DPAD + 2*BK*DPAD + BQ*PPAD) * 4)

__global__ __launch_bounds__(NTH, 1)
void fa_fwd(const float* __restrict__ Q, const float* __restrict__ K,
            const float* __restrict__ V, const int* __restrict__ qsl,
            const int* __restrict__ qln, float* __restrict__ O)
{
    extern __shared__ float sm[];
    float* q_s = sm;                       // [BQ][DPAD]
    float* k_s = q_s + BQ * DPAD;          // [BK][DPAD]
    float* v_s = k_s + BK * DPAD;          // [BK][DPAD]
    float* p_s = v_s + BK * DPAD;          // [BQ][PPAD]

    const int b    = blockIdx.z;
    const int head = blockIdx.y;
    const int qstart = qsl[b];
    const int qlen   = qln[b];
    const int kvstart = qstart;            // self-attention prefill: kv == q
    const int kvlen   = qlen;
    const int q0 = blockIdx.x * BQ;
    if (q0 >= qlen) return;
    const int kvh = head >> 2;             // NH/NKV = 4

    const int tid  = threadIdx.x;
    const int lane = tid & 31;
    const int warp = tid >> 5;
    const int qi2  = (warp << 2) + (lane >> 3);   // 0..31 -> rows 2*qi2, 2*qi2+1
    const int j    = lane & 7;                     // k-col group / d-chunk
    const int r0   = 2 * qi2;
    const int r1   = r0 + 1;

    // ---- load Q tile ----
    for (int it = tid; it < BQ * (HD / 4); it += NTH) {
        int r = it >> 5, c4 = it & 31;
        int gq = q0 + r;
        float4 val = make_float4(0.f, 0.f, 0.f, 0.f);
        if (gq < qlen)
            val = *(const float4*)&Q[((size_t)(qstart + gq) * NH + head) * HD + c4 * 4];
        *(float4*)&q_s[r * DPAD + c4 * 4] = val;
    }

    float m0 = NEGV, m1 = NEGV, l0 = 0.f, l1 = 0.f;
    float acc0[16], acc1[16];
#pragma unroll
    for (int i = 0; i < 16; i++) { acc0[i] = 0.f; acc1[i] = 0.f; }

    const int off  = kvlen - qlen;
    const int qaLo = q0 + off;
    const int qaHi = min(q0 + BQ - 1, qlen - 1) + off;
    int kmin = qaLo - (WINDOW - 1); if (kmin < 0) kmin = 0;
    const int kmax = min(kvlen - 1, qaHi);
    const float pre = QK_SCALE / SOFTCAPV;

    const int gq0 = q0 + r0;  // global (seq-local) query rows of this thread
    const int gq1 = q0 + r1;
    const int qa0 = gq0 + off;
    const int qa1 = gq1 + off;

    for (int kt = (kmin / BK) * BK; kt <= kmax; kt += BK) {
        __syncthreads();   // protect k_s/v_s (and p_s producers) from prior iter consumers
        // ---- load K,V tile ----
        for (int it = tid; it < BK * (HD / 4); it += NTH) {
            int r = it >> 5, c4 = it & 31;
            int gk = kt + r;
            float4 kv = make_float4(0.f, 0.f, 0.f, 0.f);
            float4 vv = make_float4(0.f, 0.f, 0.f, 0.f);
            if (gk < kvlen) {
                size_t base = ((size_t)(kvstart + gk) * NKV + kvh) * HD + c4 * 4;
                kv = *(const float4*)&K[base];
                vv = *(const float4*)&V[base];
            }
            *(float4*)&k_s[r * DPAD + c4 * 4] = kv;
            *(float4*)&v_s[r * DPAD + c4 * 4] = vv;
        }
        __syncthreads();

        // ---- QK^T: thread computes s[2][8], k columns kt + 8*i + j ----
        float s0[8], s1[8];
#pragma unroll
        for (int i = 0; i < 8; i++) { s0[i] = 0.f; s1[i] = 0.f; }
#pragma unroll 4
        for (int d4 = 0; d4 < 32; d4++) {
            float4 qa = *(float4*)&q_s[r0 * DPAD + d4 * 4];
            float4 qb = *(float4*)&q_s[r1 * DPAD + d4 * 4];
#pragma unroll
            for (int i = 0; i < 8; i++) {
                float4 kv = *(float4*)&k_s[(8 * i + j) * DPAD + d4 * 4];
                s0[i] = fmaf(qa.x, kv.x, fmaf(qa.y, kv.y, fmaf(qa.z, kv.z, fmaf(qa.w, kv.w, s0[i]))));
                s1[i] = fmaf(qb.x, kv.x, fmaf(qb.y, kv.y, fmaf(qb.z, kv.z, fmaf(qb.w, kv.w, s1[i]))));
            }
        }

        // ---- softcap + mask ----
#pragma unroll
        for (int i = 0; i < 8; i++) {
            int gk = kt + 8 * i + j;
            // softcap * tanh(scale*s/softcap); tanh(x) = 1 - 2/(e^{2x}+1) (overflow-safe)
            float x0 = s0[i] * pre;
            float x1 = s1[i] * pre;
            float t0 = __expf(2.f * x0);
            float t1 = __expf(2.f * x1);
            float sc0 = SOFTCAPV * (1.f - 2.f / (t0 + 1.f));
            float sc1 = SOFTCAPV * (1.f - 2.f / (t1 + 1.f));
            bool v0 = (gk <= qa0) && (qa0 - gk < WINDOW) && (gk < kvlen) && (gq0 < qlen);
            bool v1 = (gk <= qa1) && (qa1 - gk < WINDOW) && (gk < kvlen) && (gq1 < qlen);
            s0[i] = v0 ? sc0 : NEGV;
            s1[i] = v1 ? sc1 : NEGV;
        }

        // ---- online softmax (reduce over the 8 j-lanes) ----
        float tm0 = s0[0], tm1 = s1[0];
#pragma unroll
        for (int i = 1; i < 8; i++) { tm0 = fmaxf(tm0, s0[i]); tm1 = fmaxf(tm1, s1[i]); }
#pragma unroll
        for (int d = 1; d < 8; d <<= 1) {
            tm0 = fmaxf(tm0, __shfl_xor_sync(0xffffffffu, tm0, d));
            tm1 = fmaxf(tm1, __shfl_xor_sync(0xffffffffu, tm1, d));
        }
        float mn0 = fmaxf(m0, tm0);
        float mn1 = fmaxf(m1, tm1);

        float ls0 = 0.f, ls1 = 0.f;
#pragma unroll
        for (int i = 0; i < 8; i++) {
            // guard: fully-masked entries must contribute 0 even when mn == NEGV
            float p0 = (s0[i] < -1e29f) ? 0.f : __expf(s0[i] - mn0);
            float p1 = (s1[i] < -1e29f) ? 0.f : __expf(s1[i] - mn1);
            ls0 += p0; ls1 += p1;
            p_s[r0 * PPAD + 8 * i + j] = p0;
            p_s[r1 * PPAD + 8 * i + j] = p1;
        }
#pragma unroll
        for (int d = 1; d < 8; d <<= 1) {
            ls0 += __shfl_xor_sync(0xffffffffu, ls0, d);
            ls1 += __shfl_xor_sync(0xffffffffu, ls1, d);
        }
        float c0 = __expf(m0 - mn0);   // underflows to 0 when m0 == NEGV, mn0 finite
        float c1 = __expf(m1 - mn1);
        l0 = l0 * c0 + ls0;
        l1 = l1 * c1 + ls1;
        m0 = mn0; m1 = mn1;
#pragma unroll
        for (int i = 0; i < 16; i++) { acc0[i] *= c0; acc1[i] *= c1; }

        // p_s rows for this qi2 were written entirely within this warp
        __syncwarp();

        // ---- PV: thread owns rows r0,r1 and dims {32c + 4j + e} ----
#pragma unroll 4
        for (int kk = 0; kk < BK; kk++) {
            float p0 = p_s[r0 * PPAD + kk];
            float p1 = p_s[r1 * PPAD + kk];
#pragma unroll
            for (int c = 0; c < 4; c++) {
                float4 vv = *(float4*)&v_s[kk * DPAD + c * 32 + j * 4];
                acc0[c * 4 + 0] = fmaf(p0, vv.x, acc0[c * 4 + 0]);
                acc0[c * 4 + 1] = fmaf(p0, vv.y, acc0[c * 4 + 1]);
                acc0[c * 4 + 2] = fmaf(p0, vv.z, acc0[c * 4 + 2]);
                acc0[c * 4 + 3] = fmaf(p0, vv.w, acc0[c * 4 + 3]);
                acc1[c * 4 + 0] = fmaf(p1, vv.x, acc1[c * 4 + 0]);
                acc1[c * 4 + 1] = fmaf(p1, vv.y, acc1[c * 4 + 1]);
                acc1[c * 4 + 2] = fmaf(p1, vv.z, acc1[c * 4 + 2]);
                acc1[c * 4 + 3] = fmaf(p1, vv.w, acc1[c * 4 + 3]);
            }
        }
    }

    // ---- epilogue ----
    if (gq0 < qlen) {
        float inv = 1.f / l0;
        size_t base = ((size_t)(qstart + gq0) * NH + head) * HD;
#pragma unroll
        for (int c = 0; c < 4; c++) {
            float4 o;
            o.x = acc0[c * 4 + 0] * inv;
            o.y = acc0[c * 4 + 1] * inv;
            o.z = acc0[c * 4 + 2] * inv;
            o.w = acc0[c * 4 + 3] * inv;
            *(float4*)&O[base + c * 32 + j * 4] = o;
        }
    }
    if (gq1 < qlen) {
        float inv = 1.f / l1;
        size_t base = ((size_t)(qstart + gq1) * NH + head) * HD;
#pragma unroll
        for (int c = 0; c < 4; c++) {
            float4 o;
            o.x = acc1[c * 4 + 0] * inv;
            o.y = acc1[c * 4 + 1] * inv;
            o.z = acc1[c * 4 + 2] * inv;
            o.w = acc1[c * 4 + 3] * inv;
            *(float4*)&O[base + c * 32 + j * 4] = o;
        }
    }
}

extern "C" void kernel_launch(void* const* d_in, const int* in_sizes, int n_in,
                              void* d_out, int out_size)
{
    const float* Q   = (const float*)d_in[0];
    const float* K   = (const float*)d_in[1];
    const float* V   = (const float*)d_in[2];
    const int*   qsl = (const int*)d_in[3];
    const int*   qln = (const int*)d_in[4];
    float* O = (float*)d_out;

    int B     = in_sizes[3];
    int total = in_sizes[0] / (NH * HD);
    int qtiles = (total + BQ - 1) / BQ;   // conservative upper bound; blocks past qlen exit

    cudaFuncSetAttribute(fa_fwd, cudaFuncAttributeMaxDynamicSharedMemorySize, SMEM_BYTES);
    dim3 grid(qtiles, NH, B);
    fa_fwd<<<grid, NTH, SMEM_BYTES>>>(Q, K, V, qsl, qln, O);
}

// round 2
// speedup vs baseline: 3.2469x; 3.2469x over previous
#include <cuda_runtime.h>
#include <cuda_bf16.h>
#include <stdint.h>

// FlashAttention varlen prefill, GQA 16/4, D=128, window 1024, softcap 30.
// Round 2: tf32 mma.sync tensor-core kernel. BQ=128 x BK=64, 8 warps,
// warp-private 16 query rows (no cross-warp softmax), P via smem round-trip.

#define NH      16
#define NKV     4
#define HD      128
#define BQ      128
#define BK      64
#define QSTR    132   // stride % 32 == 4 -> conflict-free A-frag loads
#define KSTR    132   // stride % 32 == 4 -> conflict-free QK B-frag loads
#define VSTR    136   // stride % 32 == 8 -> conflict-free PV B-frag loads
#define PSTR    68    // stride % 32 == 4 -> conflict-free PV A-frag loads
#define NTH     256
#define WINDOW  1024
#define CAPV    30.0f
#define NEGV    (-1e30f)
#define SCALE   0.08838834764831845f          // 1/sqrt(128)
#define PRE2    (2.0f * SCALE / CAPV)         // tanh via exp(2z)

#define SMEM_FLOATS (BQ*QSTR + BK*KSTR + BK*VSTR + BQ*PSTR)
#define SMEM_BYTES  (SMEM_FLOATS * 4)

__device__ __forceinline__ float tf32r(float x) {
    uint32_t r;
    asm("cvt.rna.tf32.f32 %0, %1;" : "=r"(r) : "f"(x));
    return __uint_as_float(r);
}

__device__ __forceinline__ void mma8(float c[4],
                                     uint32_t a0, uint32_t a1, uint32_t a2, uint32_t a3,
                                     uint32_t b0, uint32_t b1) {
    asm volatile(
        "mma.sync.aligned.m16n8k8.row.col.f32.tf32.tf32.f32 "
        "{%0,%1,%2,%3}, {%4,%5,%6,%7}, {%8,%9}, {%0,%1,%2,%3};"
        : "+f"(c[0]), "+f"(c[1]), "+f"(c[2]), "+f"(c[3])
        : "r"(a0), "r"(a1), "r"(a2), "r"(a3), "r"(b0), "r"(b1));
}

__global__ __launch_bounds__(NTH, 1)
void fa_fwd(const float* __restrict__ Q, const float* __restrict__ K,
            const float* __restrict__ V, const int* __restrict__ qsl,
            const int* __restrict__ qln, float* __restrict__ O)
{
    extern __shared__ float sm[];
    float* q_s = sm;                    // [BQ][QSTR]
    float* k_s = q_s + BQ * QSTR;       // [BK][KSTR]
    float* v_s = k_s + BK * KSTR;       // [BK][VSTR]
    float* p_s = v_s + BK * VSTR;       // [BQ][PSTR]

    const int b      = blockIdx.z;
    const int head   = blockIdx.y;
    const int qstart = qsl[b];
    const int qlen   = qln[b];
    const int kvstart = qstart;         // self-attention prefill
    const int kvlen   = qlen;
    const int q0 = blockIdx.x * BQ;
    if (q0 >= qlen) return;
    const int kvh = head >> 2;          // GQA group of 4

    const int tid  = threadIdx.x;
    const int lane = tid & 31;
    const int w    = tid >> 5;
    const int g    = lane >> 2;         // groupID (0..7)
    const int tig  = lane & 3;          // thread-in-group (0..3)
    const int lr0  = w * 16 + g;        // this thread's tile rows
    const int lr1  = lr0 + 8;
    const int gq0  = q0 + lr0;          // seq-local query indices
    const int gq1  = q0 + lr1;

    // ---- load Q tile (tf32-rounded fp32 in smem) ----
    for (int it = tid; it < BQ * (HD / 4); it += NTH) {
        int r = it >> 5, c4 = it & 31;
        int gq = q0 + r;
        float4 val = make_float4(0.f, 0.f, 0.f, 0.f);
        if (gq < qlen)
            val = *(const float4*)&Q[((size_t)(qstart + gq) * NH + head) * HD + c4 * 4];
        float* dst = &q_s[r * QSTR + c4 * 4];
        dst[0] = tf32r(val.x); dst[1] = tf32r(val.y);
        dst[2] = tf32r(val.z); dst[3] = tf32r(val.w);
    }

    float oacc[16][4];
#pragma unroll
    for (int i = 0; i < 16; i++)
#pragma unroll
        for (int d = 0; d < 4; d++) oacc[i][d] = 0.f;
    float m0 = NEGV, m1 = NEGV, l0 = 0.f, l1 = 0.f;

    const int off  = kvlen - qlen;
    const int qa0  = gq0 + off;
    const int qa1  = gq1 + off;
    const int qaLo = q0 + off;
    const int qaHi = min(q0 + BQ - 1, qlen - 1) + off;
    int kmin = qaLo - (WINDOW - 1); if (kmin < 0) kmin = 0;
    const int kmax = min(kvlen - 1, qaHi);
    const bool qv0 = (gq0 < qlen);
    const bool qv1 = (gq1 < qlen);

    for (int kt = (kmin / BK) * BK; kt <= kmax; kt += BK) {
        __syncthreads();
        // ---- load K,V tile ----
        for (int it = tid; it < BK * (HD / 4); it += NTH) {
            int r = it >> 5, c4 = it & 31;
            int gk = kt + r;
            float4 kv = make_float4(0.f, 0.f, 0.f, 0.f);
            float4 vv = make_float4(0.f, 0.f, 0.f, 0.f);
            if (gk < kvlen) {
                size_t base = ((size_t)(kvstart + gk) * NKV + kvh) * HD + c4 * 4;
                kv = *(const float4*)&K[base];
                vv = *(const float4*)&V[base];
            }
            float* kd = &k_s[r * KSTR + c4 * 4];
            kd[0] = tf32r(kv.x); kd[1] = tf32r(kv.y);
            kd[2] = tf32r(kv.z); kd[3] = tf32r(kv.w);
            float* vd = &v_s[r * VSTR + c4 * 4];
            vd[0] = tf32r(vv.x); vd[1] = tf32r(vv.y);
            vd[2] = tf32r(vv.z); vd[3] = tf32r(vv.w);
        }
        __syncthreads();

        // ---- QK^T: warp computes S[16][64] as 8 n-tiles x 16 k-steps ----
        float sacc[8][4];
#pragma unroll
        for (int nt = 0; nt < 8; nt++)
#pragma unroll
            for (int d = 0; d < 4; d++) sacc[nt][d] = 0.f;

#pragma unroll
        for (int kk = 0; kk < 16; kk++) {
            uint32_t a0 = __float_as_uint(q_s[lr0 * QSTR + kk * 8 + tig]);
            uint32_t a1 = __float_as_uint(q_s[lr1 * QSTR + kk * 8 + tig]);
            uint32_t a2 = __float_as_uint(q_s[lr0 * QSTR + kk * 8 + tig + 4]);
            uint32_t a3 = __float_as_uint(q_s[lr1 * QSTR + kk * 8 + tig + 4]);
#pragma unroll
            for (int nt = 0; nt < 8; nt++) {
                uint32_t b0 = __float_as_uint(k_s[(nt * 8 + g) * KSTR + kk * 8 + tig]);
                uint32_t b1 = __float_as_uint(k_s[(nt * 8 + g) * KSTR + kk * 8 + tig + 4]);
                mma8(sacc[nt], a0, a1, a2, a3, b0, b1);
            }
        }

        // ---- softcap + mask; track row maxima ----
        float mx0 = NEGV, mx1 = NEGV;
#pragma unroll
        for (int nt = 0; nt < 8; nt++) {
            int colbase = kt + nt * 8 + 2 * tig;
#pragma unroll
            for (int d = 0; d < 4; d++) {
                float s  = sacc[nt][d];
                int col  = colbase + (d & 1);
                int qa   = (d < 2) ? qa0 : qa1;
                bool okq = (d < 2) ? qv0 : qv1;
                // softcap: C*tanh(s*scale/C) = C - 2C/(exp(2*s*scale/C)+1)
                float u = __expf(s * PRE2);
                float logit = CAPV - __fdividef(2.0f * CAPV, u + 1.0f);
                bool ok = (col <= qa) && (qa - col < WINDOW) && (col < kvlen) && okq;
                s = ok ? logit : NEGV;
                sacc[nt][d] = s;
                if (d < 2) mx0 = fmaxf(mx0, s); else mx1 = fmaxf(mx1, s);
            }
        }
        mx0 = fmaxf(mx0, __shfl_xor_sync(0xffffffffu, mx0, 1));
        mx0 = fmaxf(mx0, __shfl_xor_sync(0xffffffffu, mx0, 2));
        mx1 = fmaxf(mx1, __shfl_xor_sync(0xffffffffu, mx1, 1));
        mx1 = fmaxf(mx1, __shfl_xor_sync(0xffffffffu, mx1, 2));

        float mn0 = fmaxf(m0, mx0);
        float mn1 = fmaxf(m1, mx1);
        float c0 = __expf(m0 - mn0);   // 0 when m was NEGV and mn finite; 1 if both NEGV
        float c1 = __expf(m1 - mn1);

        // ---- exp + P store (tf32) + row sums ----
        float sum0 = 0.f, sum1 = 0.f;
#pragma unroll
        for (int nt = 0; nt < 8; nt++) {
            float p0 = (sacc[nt][0] < -1e29f) ? 0.f : __expf(sacc[nt][0] - mn0);
            float p1 = (sacc[nt][1] < -1e29f) ? 0.f : __expf(sacc[nt][1] - mn0);
            float p2 = (sacc[nt][2] < -1e29f) ? 0.f : __expf(sacc[nt][2] - mn1);
            float p3 = (sacc[nt][3] < -1e29f) ? 0.f : __expf(sacc[nt][3] - mn1);
            sum0 += p0 + p1;
            sum1 += p2 + p3;
            float2 w0; w0.x = tf32r(p0); w0.y = tf32r(p1);
            float2 w1; w1.x = tf32r(p2); w1.y = tf32r(p3);
            *(float2*)&p_s[lr0 * PSTR + nt * 8 + 2 * tig] = w0;
            *(float2*)&p_s[lr1 * PSTR + nt * 8 + 2 * tig] = w1;
        }
        sum0 += __shfl_xor_sync(0xffffffffu, sum0, 1);
        sum0 += __shfl_xor_sync(0xffffffffu, sum0, 2);
        sum1 += __shfl_xor_sync(0xffffffffu, sum1, 1);
        sum1 += __shfl_xor_sync(0xffffffffu, sum1, 2);

        l0 = l0 * c0 + sum0;
        l1 = l1 * c1 + sum1;
        m0 = mn0; m1 = mn1;
#pragma unroll
        for (int nt = 0; nt < 16; nt++) {
            oacc[nt][0] *= c0; oacc[nt][1] *= c0;
            oacc[nt][2] *= c1; oacc[nt][3] *= c1;
        }

        __syncwarp();   // P rows are warp-private: produce->consume within warp

        // ---- PV: O[16][128] += P[16][64] x V[64][128] ----
#pragma unroll
        for (int kk = 0; kk < 8; kk++) {
            uint32_t a0 = __float_as_uint(p_s[lr0 * PSTR + kk * 8 + tig]);
            uint32_t a1 = __float_as_uint(p_s[lr1 * PSTR + kk * 8 + tig]);
            uint32_t a2 = __float_as_uint(p_s[lr0 * PSTR + kk * 8 + tig + 4]);
            uint32_t a3 = __float_as_uint(p_s[lr1 * PSTR + kk * 8 + tig + 4]);
#pragma unroll
            for (int nt = 0; nt < 16; nt++) {
                uint32_t b0 = __float_as_uint(v_s[(kk * 8 + tig) * VSTR + nt * 8 + g]);
                uint32_t b1 = __float_as_uint(v_s[(kk * 8 + tig + 4) * VSTR + nt * 8 + g]);
                mma8(oacc[nt], a0, a1, a2, a3, b0, b1);
            }
        }
        __syncwarp();   // finish reading p_s before next iter overwrites (same warp)
    }

    // ---- epilogue ----
    if (qv0) {
        float inv = 1.f / l0;
        size_t base = ((size_t)(qstart + gq0) * NH + head) * HD;
#pragma unroll
        for (int nt = 0; nt < 16; nt++) {
            float2 o; o.x = oacc[nt][0] * inv; o.y = oacc[nt][1] * inv;
            *(float2*)&O[base + nt * 8 + 2 * tig] = o;
        }
    }
    if (qv1) {
        float inv = 1.f / l1;
        size_t base = ((size_t)(qstart + gq1) * NH + head) * HD;
#pragma unroll
        for (int nt = 0; nt < 16; nt++) {
            float2 o; o.x = oacc[nt][2] * inv; o.y = oacc[nt][3] * inv;
            *(float2*)&O[base + nt * 8 + 2 * tig] = o;
        }
    }
}

extern "C" void kernel_launch(void* const* d_in, const int* in_sizes, int n_in,
                              void* d_out, int out_size)
{
    const float* Q   = (const float*)d_in[0];
    const float* K   = (const float*)d_in[1];
    const float* V   = (const float*)d_in[2];
    const int*   qsl = (const int*)d_in[3];
    const int*   qln = (const int*)d_in[4];
    float* O = (float*)d_out;

    int B     = in_sizes[3];
    int total = in_sizes[0] / (NH * HD);
    int qtiles = (total + BQ - 1) / BQ;   // upper bound; blocks past qlen exit

    cudaFuncSetAttribute(fa_fwd, cudaFuncAttributeMaxDynamicSharedMemorySize, SMEM_BYTES);
    dim3 grid(qtiles, NH, B);
    fa_fwd<<<grid, NTH, SMEM_BYTES>>>(Q, K, V, qsl, qln, O);
}